// round 6
// baseline (speedup 1.0000x reference)
#include <cuda_runtime.h>
#include <math.h>

#define W_   512
#define H_   512
#define HW_  (512 * 512)
#define EPS  1e-8f
#define TW   26              // output columns per warp (26 + 6 halo = 32 lanes)
#define FULLMASK 0xffffffffu

__device__ __forceinline__ float sqrt_approx(float x) {
    float r;
    asm("sqrt.approx.f32 %0, %1;" : "=f"(r) : "f"(x));
    return r;
}

// h[L] = sum_{k=0..6} v[L+k] over the warp-distributed 32-vector.
// Lanes >= 26 get garbage (shfl self) — outputs there are predicated off.
__device__ __forceinline__ float hsum7(float v) {
    float d1 = v + __shfl_down_sync(FULLMASK, v, 1);     // 2-sum
    float d2 = d1 + __shfl_down_sync(FULLMASK, d1, 2);   // 4-sum
    float r4 = __shfl_down_sync(FULLMASK, d1, 4);        // v[c+4]+v[c+5]
    float r6 = __shfl_down_sync(FULLMASK, v, 6);         // v[c+6]
    return d2 + (r4 + r6);
}

__device__ __forceinline__ float smooth_l1(float a, float b) {
    float d = a - b;
    float ad = fabsf(d);
    return (ad < 1.0f) ? 0.5f * d * d : ad - 0.5f;
}

// ---------------- interior (no-guard) row step ----------------
template <int S, bool EMIT>
__device__ __forceinline__ void row_fast(
    const float* __restrict__ P, const float* __restrict__ T,
    int& off, float (&ring)[4][7], float (&vs)[4],
    float& acc, bool out_ok, float inv_n)
{
    float a0 = P[off], a1 = P[off + HW_], a2 = P[off + 2 * HW_];
    float b0 = T[off], b1 = T[off + HW_], b2 = T[off + 2 * HW_];

    float vP  = a0 + a1 + a2;
    float v2P = fmaf(a0, a0, fmaf(a1, a1, a2 * a2));
    float vT  = b0 + b1 + b2;
    float v2T = fmaf(b0, b0, fmaf(b1, b1, b2 * b2));

    float h0 = hsum7(vP);
    float h1 = hsum7(v2P);
    float h2 = hsum7(vT);
    float h3 = hsum7(v2T);

    vs[0] += h0 - ring[0][S]; ring[0][S] = h0;
    vs[1] += h1 - ring[1][S]; ring[1][S] = h1;
    vs[2] += h2 - ring[2][S]; ring[2][S] = h2;
    vs[3] += h3 - ring[3][S]; ring[3][S] = h3;

    if (EMIT) {
        float mp = vs[0] * inv_n;
        float sp = sqrt_approx(fmaf(-mp, mp, vs[1] * inv_n) + EPS);
        float mt = vs[2] * inv_n;
        float st = sqrt_approx(fmaf(-mt, mt, vs[3] * inv_n) + EPS);
        float f = smooth_l1(sp, st);
        acc += out_ok ? f : 0.f;
    }
    off += W_;
}

// ---------------- border (guarded) row step — round-3 verbatim ----------------
template <int S>
__device__ __forceinline__ void rowstep(
    const float* __restrict__ P, const float* __restrict__ T,
    int gx, bool okx, bool out_ok, int oy0,
    int& i, float (&ring)[4][7], float (&vs)[4], float& acc, float inv_n)
{
    const int gy = oy0 - 3 + i;
    const bool ok = okx && (gy >= 0) && (gy < H_);
    const int off = (gy << 9) + gx;

    float h[4];
    {
        float a0 = ok ? P[off]           : 0.f;
        float a1 = ok ? P[off + HW_]     : 0.f;
        float a2 = ok ? P[off + 2 * HW_] : 0.f;
        float v  = a0 + a1 + a2;
        float v2 = fmaf(a0, a0, fmaf(a1, a1, a2 * a2));
        h[0] = hsum7(v);
        h[1] = hsum7(v2);
    }
    {
        float a0 = ok ? T[off]           : 0.f;
        float a1 = ok ? T[off + HW_]     : 0.f;
        float a2 = ok ? T[off + 2 * HW_] : 0.f;
        float v  = a0 + a1 + a2;
        float v2 = fmaf(a0, a0, fmaf(a1, a1, a2 * a2));
        h[2] = hsum7(v);
        h[3] = hsum7(v2);
    }

#pragma unroll
    for (int a = 0; a < 4; a++) {
        vs[a] += h[a] - ring[a][S];
        ring[a][S] = h[a];
    }

    if (i >= 6 && out_ok) {
        float mp = vs[0] * inv_n;
        float sp = sqrt_approx(fmaf(-mp, mp, vs[1] * inv_n) + EPS);
        float mt = vs[2] * inv_n;
        float st = sqrt_approx(fmaf(-mt, mt, vs[3] * inv_n) + EPS);
        acc += smooth_l1(sp, st);
    }
    i++;
}

__global__ __launch_bounds__(128, 6)
void dist_loss_kernel(const float* __restrict__ pred,
                      const float* __restrict__ tgt,
                      float* __restrict__ out)
{
    const int L  = threadIdx.x & 31;
    const int w  = threadIdx.x >> 5;
    const int x0 = blockIdx.x * TW;
    const int oy0 = (blockIdx.y << 7) + (w << 5);     // warp's first output row
    const size_t bofs = (size_t)blockIdx.z * 3 * HW_;
    const float* P = pred + bofs;
    const float* T = tgt + bofs;

    const int gx = x0 - 3 + L;                        // halo-inclusive column
    const float inv_n = 1.0f / 147.0f;

    float ring[4][7];
    float vs[4];
#pragma unroll
    for (int a = 0; a < 4; a++) {
        vs[a] = 0.f;
#pragma unroll
        for (int j = 0; j < 7; j++) ring[a][j] = 0.f;
    }

    float acc = 0.f;

    // warp-uniform interior test: all 38 gy in range, all 32 gx in range
    const bool interior = (oy0 > 0) && (oy0 < 480) &&
                          (blockIdx.x > 0) && (blockIdx.x < 19);

    if (interior) {
        const bool out_ok = (L < TW);
        int off = ((oy0 - 3) << 9) + gx;
        // prologue: 7 rows, emit starts at the 7th
        row_fast<0, false>(P, T, off, ring, vs, acc, out_ok, inv_n);
        row_fast<1, false>(P, T, off, ring, vs, acc, out_ok, inv_n);
        row_fast<2, false>(P, T, off, ring, vs, acc, out_ok, inv_n);
        row_fast<3, false>(P, T, off, ring, vs, acc, out_ok, inv_n);
        row_fast<4, false>(P, T, off, ring, vs, acc, out_ok, inv_n);
        row_fast<5, false>(P, T, off, ring, vs, acc, out_ok, inv_n);
        row_fast<6, true >(P, T, off, ring, vs, acc, out_ok, inv_n);
#pragma unroll 1
        for (int c = 0; c < 4; c++) {
            row_fast<0, true>(P, T, off, ring, vs, acc, out_ok, inv_n);
            row_fast<1, true>(P, T, off, ring, vs, acc, out_ok, inv_n);
            row_fast<2, true>(P, T, off, ring, vs, acc, out_ok, inv_n);
            row_fast<3, true>(P, T, off, ring, vs, acc, out_ok, inv_n);
            row_fast<4, true>(P, T, off, ring, vs, acc, out_ok, inv_n);
            row_fast<5, true>(P, T, off, ring, vs, acc, out_ok, inv_n);
            row_fast<6, true>(P, T, off, ring, vs, acc, out_ok, inv_n);
        }
        row_fast<0, true>(P, T, off, ring, vs, acc, out_ok, inv_n);
        row_fast<1, true>(P, T, off, ring, vs, acc, out_ok, inv_n);
        row_fast<2, true>(P, T, off, ring, vs, acc, out_ok, inv_n);
    } else {
        const bool okx = (gx >= 0) && (gx < W_);
        const bool out_ok = (L < TW) && ((x0 + L) < W_);
        int i = 0;
#pragma unroll 1
        for (int c = 0; c < 5; c++) {
            rowstep<0>(P, T, gx, okx, out_ok, oy0, i, ring, vs, acc, inv_n);
            rowstep<1>(P, T, gx, okx, out_ok, oy0, i, ring, vs, acc, inv_n);
            rowstep<2>(P, T, gx, okx, out_ok, oy0, i, ring, vs, acc, inv_n);
            rowstep<3>(P, T, gx, okx, out_ok, oy0, i, ring, vs, acc, inv_n);
            rowstep<4>(P, T, gx, okx, out_ok, oy0, i, ring, vs, acc, inv_n);
            rowstep<5>(P, T, gx, okx, out_ok, oy0, i, ring, vs, acc, inv_n);
            rowstep<6>(P, T, gx, okx, out_ok, oy0, i, ring, vs, acc, inv_n);
        }
        rowstep<0>(P, T, gx, okx, out_ok, oy0, i, ring, vs, acc, inv_n);
        rowstep<1>(P, T, gx, okx, out_ok, oy0, i, ring, vs, acc, inv_n);
        rowstep<2>(P, T, gx, okx, out_ok, oy0, i, ring, vs, acc, inv_n);
    }

    // warp + block reduce
#pragma unroll
    for (int o = 16; o > 0; o >>= 1)
        acc += __shfl_xor_sync(FULLMASK, acc, o);

    __shared__ float ws[4];
    if (L == 0) ws[w] = acc;
    __syncthreads();
    if (threadIdx.x == 0) {
        float s = ws[0] + ws[1] + ws[2] + ws[3];
        atomicAdd(out, s * (1.0f / (16.0f * 512.0f * 512.0f)));
    }
}

extern "C" void kernel_launch(void* const* d_in, const int* in_sizes, int n_in,
                              void* d_out, int out_size)
{
    const float* pred = (const float*)d_in[0];
    const float* tgt  = (const float*)d_in[1];
    float* out = (float*)d_out;

    cudaMemsetAsync(out, 0, sizeof(float));

    dim3 block(128, 1, 1);
    dim3 grid((W_ + TW - 1) / TW, H_ / 128, 16);   // 20 x 4 x 16 = 1280 CTAs
    dist_loss_kernel<<<grid, block>>>(pred, tgt, out);
}

// round 7
// speedup vs baseline: 2.3215x; 2.3215x over previous
#include <cuda_runtime.h>
#include <math.h>

#define W_   512
#define H_   512
#define HW_  (512 * 512)
#define EPS  1e-8f
#define TW   26              // output columns per warp (26 + 6 halo = 32 lanes)
#define FULLMASK 0xffffffffu

__device__ __forceinline__ float sqrt_approx(float x) {
    float r;
    asm("sqrt.approx.f32 %0, %1;" : "=f"(r) : "f"(x));
    return r;
}

// h[L] = sum_{k=0..6} v[L+k] over the warp-distributed 32-vector.
// Lanes >= 26 get garbage (shfl self) — outputs there are predicated off.
__device__ __forceinline__ float hsum7(float v) {
    float d1 = v + __shfl_down_sync(FULLMASK, v, 1);     // 2-sum
    float d2 = d1 + __shfl_down_sync(FULLMASK, d1, 2);   // 4-sum
    float r4 = __shfl_down_sync(FULLMASK, d1, 4);        // v[c+4]+v[c+5]
    float r6 = __shfl_down_sync(FULLMASK, v, 6);         // v[c+6]
    return d2 + (r4 + r6);
}

__device__ __forceinline__ float smooth_l1(float a, float b) {
    float d = a - b;
    float ad = fabsf(d);
    return (ad < 1.0f) ? 0.5f * d * d : ad - 0.5f;
}

struct Six { float a0, a1, a2, b0, b1, b2; };

__device__ __forceinline__ Six ld6(const float* __restrict__ P,
                                   const float* __restrict__ T,
                                   int off, bool ok) {
    Six s;
    s.a0 = ok ? P[off]           : 0.f;
    s.a1 = ok ? P[off + HW_]     : 0.f;
    s.a2 = ok ? P[off + 2 * HW_] : 0.f;
    s.b0 = ok ? T[off]           : 0.f;
    s.b1 = ok ? T[off + HW_]     : 0.f;
    s.b2 = ok ? T[off + 2 * HW_] : 0.f;
    return s;
}

// One row step with depth-1 load pipelining: consume `nxt` (row i's data,
// loaded last step), immediately issue loads for row i+1 into `nxt`, then
// compute row i (hsum7, ring slot S, vertical sums, emit when i >= 6).
template <int S>
__device__ __forceinline__ void rowstep(
    const float* __restrict__ P, const float* __restrict__ T,
    int gx, bool okx, bool out_ok, int oy0,
    int& i, Six& nxt, float (&ring)[4][7], float (&vs)[4],
    float& acc, float inv_n)
{
    Six cur = nxt;

    // prefetch row i+1 (the very last prefetch of row 38 is discarded;
    // its guard keeps any OOB access predicated off)
    {
        const int gy1 = oy0 - 2 + i;              // (oy0 - 3) + (i + 1)
        const bool ok1 = okx && (gy1 >= 0) && (gy1 < H_);
        nxt = ld6(P, T, (gy1 << 9) + gx, ok1);
    }

    // compute row i from cur
    float h0, h1, h2, h3;
    {
        float v  = cur.a0 + cur.a1 + cur.a2;
        float v2 = fmaf(cur.a0, cur.a0, fmaf(cur.a1, cur.a1, cur.a2 * cur.a2));
        h0 = hsum7(v);
        h1 = hsum7(v2);
    }
    {
        float v  = cur.b0 + cur.b1 + cur.b2;
        float v2 = fmaf(cur.b0, cur.b0, fmaf(cur.b1, cur.b1, cur.b2 * cur.b2));
        h2 = hsum7(v);
        h3 = hsum7(v2);
    }

    vs[0] += h0 - ring[0][S]; ring[0][S] = h0;
    vs[1] += h1 - ring[1][S]; ring[1][S] = h1;
    vs[2] += h2 - ring[2][S]; ring[2][S] = h2;
    vs[3] += h3 - ring[3][S]; ring[3][S] = h3;

    if (i >= 6 && out_ok) {
        float mp = vs[0] * inv_n;
        float sp = sqrt_approx(fmaf(-mp, mp, vs[1] * inv_n) + EPS);
        float mt = vs[2] * inv_n;
        float st = sqrt_approx(fmaf(-mt, mt, vs[3] * inv_n) + EPS);
        acc += smooth_l1(sp, st);
    }
    i++;
}

__global__ __launch_bounds__(128, 6)
void dist_loss_kernel(const float* __restrict__ pred,
                      const float* __restrict__ tgt,
                      float* __restrict__ out)
{
    const int L  = threadIdx.x & 31;
    const int w  = threadIdx.x >> 5;
    const int x0 = blockIdx.x * TW;
    const int oy0 = (blockIdx.y << 7) + (w << 5);     // warp's first output row
    const size_t bofs = (size_t)blockIdx.z * 3 * HW_;
    const float* P = pred + bofs;
    const float* T = tgt + bofs;

    const int gx = x0 - 3 + L;                        // halo-inclusive column
    const bool okx = (gx >= 0) && (gx < W_);
    const bool out_ok = (L < TW) && ((x0 + L) < W_);

    const float inv_n = 1.0f / 147.0f;

    float ring[4][7];
    float vs[4];
#pragma unroll
    for (int a = 0; a < 4; a++) {
        vs[a] = 0.f;
#pragma unroll
        for (int j = 0; j < 7; j++) ring[a][j] = 0.f;
    }

    float acc = 0.f;
    int i = 0;

    // prime the pipeline with row 0
    Six nxt;
    {
        const int gy0 = oy0 - 3;
        const bool ok0 = okx && (gy0 >= 0);
        nxt = ld6(P, T, (gy0 << 9) + gx, ok0);
    }

    // 38 input rows = 5 chunks of 7 ring slots + 3 tail steps
#pragma unroll 1
    for (int c = 0; c < 5; c++) {
        rowstep<0>(P, T, gx, okx, out_ok, oy0, i, nxt, ring, vs, acc, inv_n);
        rowstep<1>(P, T, gx, okx, out_ok, oy0, i, nxt, ring, vs, acc, inv_n);
        rowstep<2>(P, T, gx, okx, out_ok, oy0, i, nxt, ring, vs, acc, inv_n);
        rowstep<3>(P, T, gx, okx, out_ok, oy0, i, nxt, ring, vs, acc, inv_n);
        rowstep<4>(P, T, gx, okx, out_ok, oy0, i, nxt, ring, vs, acc, inv_n);
        rowstep<5>(P, T, gx, okx, out_ok, oy0, i, nxt, ring, vs, acc, inv_n);
        rowstep<6>(P, T, gx, okx, out_ok, oy0, i, nxt, ring, vs, acc, inv_n);
    }
    rowstep<0>(P, T, gx, okx, out_ok, oy0, i, nxt, ring, vs, acc, inv_n);
    rowstep<1>(P, T, gx, okx, out_ok, oy0, i, nxt, ring, vs, acc, inv_n);
    rowstep<2>(P, T, gx, okx, out_ok, oy0, i, nxt, ring, vs, acc, inv_n);

    // warp + block reduce
#pragma unroll
    for (int o = 16; o > 0; o >>= 1)
        acc += __shfl_xor_sync(FULLMASK, acc, o);

    __shared__ float ws[4];
    if (L == 0) ws[w] = acc;
    __syncthreads();
    if (threadIdx.x == 0) {
        float s = ws[0] + ws[1] + ws[2] + ws[3];
        atomicAdd(out, s * (1.0f / (16.0f * 512.0f * 512.0f)));
    }
}

extern "C" void kernel_launch(void* const* d_in, const int* in_sizes, int n_in,
                              void* d_out, int out_size)
{
    const float* pred = (const float*)d_in[0];
    const float* tgt  = (const float*)d_in[1];
    float* out = (float*)d_out;

    cudaMemsetAsync(out, 0, sizeof(float));

    dim3 block(128, 1, 1);
    dim3 grid((W_ + TW - 1) / TW, H_ / 128, 16);   // 20 x 4 x 16 = 1280 CTAs
    dist_loss_kernel<<<grid, block>>>(pred, tgt, out);
}